// round 5
// baseline (speedup 1.0000x reference)
#include <cuda_runtime.h>
#include <math.h>

// Problem constants
#define Bsz 8
#define Sq  2048
#define Dm  256
#define Hh  4
#define Dk  64
#define NTOK (Bsz*Sq)          // 16384
#define OUT0_ELEMS ((size_t)NTOK*Dm) // 4194304
#define NROWS (Bsz*Hh*Sq)      // 65536 (b,h,q) rows
#define NXT 16                 // k-tiles per score row (2048/128)

// ---------------- scratch (static device globals; allocation-free contract) ---
__device__ float g_Q[(size_t)Bsz*Hh*Sq*Dk];   // (b,h,q,d) 16MB
__device__ float g_K[(size_t)Bsz*Hh*Sq*Dk];   // 16MB
__device__ float g_V[(size_t)NTOK*Dm];        // 16MB
__device__ float g_E[(size_t)Bsz*Hh*Sq*Sq];   // exp(scores), 512MiB
__device__ float g_O[(size_t)NTOK*Dm];        // attn output pre-proj, 16MB
__device__ float g_Zp[(size_t)NXT*NROWS];     // per-k-tile row-sum partials, 4MB
__device__ float g_RZ[(size_t)NROWS];         // 0.25 / rowsum

// =============================================================================
// helpers
// =============================================================================
__device__ __forceinline__ unsigned f2tf(float f) {
    unsigned u;
    asm("cvt.rna.tf32.f32 %0, %1;" : "=r"(u) : "f"(f));
    return u;
}
__device__ __forceinline__ void mma_tf32(float c[4],
    unsigned a0, unsigned a1, unsigned a2, unsigned a3,
    unsigned b0, unsigned b1)
{
    asm volatile(
        "mma.sync.aligned.m16n8k8.row.col.f32.tf32.tf32.f32 "
        "{%0,%1,%2,%3},{%4,%5,%6,%7},{%8,%9},{%0,%1,%2,%3};"
        : "+f"(c[0]), "+f"(c[1]), "+f"(c[2]), "+f"(c[3])
        : "r"(a0), "r"(a1), "r"(a2), "r"(a3), "r"(b0), "r"(b1));
}
__device__ __forceinline__ void cp_async16(void* smem, const void* gmem) {
    unsigned saddr = (unsigned)__cvta_generic_to_shared(smem);
    asm volatile("cp.async.cg.shared.global [%0], [%1], 16;\n"
                 :: "r"(saddr), "l"(gmem));
}
__device__ __forceinline__ void cp_commit() {
    asm volatile("cp.async.commit_group;\n");
}
template<int N>
__device__ __forceinline__ void cp_wait() {
    asm volatile("cp.async.wait_group %0;\n" :: "n"(N));
}
__device__ __forceinline__ float warp_sum(float v) {
#pragma unroll
    for (int o = 16; o; o >>= 1) v += __shfl_xor_sync(0xffffffffu, v, o);
    return v;
}

#define STAGES 4

// =============================================================================
// Fused QKV projection: one launch, grid.z in {0,1,2} selects (input, W, bias,
// output). z<2 scatters head-major (Q,K); z==2 row-major (V).
// 128x128 block, 4 warps, 64x64 warp tile, BK=16, 4-stage cp.async. K=Dm=256.
// =============================================================================
__global__ void __launch_bounds__(128, 2) qkv_proj_kernel(
    const float* __restrict__ q, const float* __restrict__ k, const float* __restrict__ v,
    const float* __restrict__ Wq, const float* __restrict__ Wk, const float* __restrict__ Wv,
    const float* __restrict__ bq, const float* __restrict__ bk, const float* __restrict__ bv,
    float* __restrict__ Cq, float* __restrict__ Ck, float* __restrict__ Cv)
{
    extern __shared__ float dsm[];
    float (*As)[128][20]  = (float(*)[128][20])dsm;
    float (*Bs)[16][136]  = (float(*)[16][136])(dsm + STAGES * 128 * 20);

    const int sel = blockIdx.z;
    const float* A    = sel == 0 ? q  : sel == 1 ? k  : v;
    const float* B    = sel == 0 ? Wq : sel == 1 ? Wk : Wv;
    const float* bias = sel == 0 ? bq : sel == 1 ? bk : bv;
    float*       C    = sel == 0 ? Cq : sel == 1 ? Ck : Cv;
    const bool scatter = sel < 2;

    const int tid  = threadIdx.x;
    const int lane = tid & 31;
    const int wid  = tid >> 5;
    const int g = lane >> 2, t = lane & 3;
    const int m0 = (wid & 1) * 64;
    const int n0 = (wid >> 1) * 64;

    const float* Ab = A + (size_t)blockIdx.y * 128 * Dm;
    const float* Bb = B + blockIdx.x * 128;

    const int arow = tid >> 2;
    const int acol = (tid & 3) * 4;
    const int brow = tid >> 5;
    const int bcol = (tid & 31) * 4;

    const int NKT = Dm / 16;   // 16

    auto issue = [&](int kt, int st) {
#pragma unroll
        for (int i = 0; i < 4; i++)
            cp_async16(&As[st][arow + 32 * i][acol],
                       Ab + (size_t)(arow + 32 * i) * Dm + kt * 16 + acol);
#pragma unroll
        for (int i = 0; i < 4; i++)
            cp_async16(&Bs[st][brow + 4 * i][bcol],
                       Bb + (size_t)(kt * 16 + brow + 4 * i) * Dm + bcol);
        cp_commit();
    };

#pragma unroll
    for (int s = 0; s < STAGES - 1; ++s) issue(s, s);

    float acc[4][8][4];
#pragma unroll
    for (int mi = 0; mi < 4; mi++)
#pragma unroll
        for (int ni = 0; ni < 8; ni++)
#pragma unroll
            for (int r = 0; r < 4; r++) acc[mi][ni][r] = 0.f;

    for (int kt = 0; kt < NKT; ++kt) {
        cp_wait<STAGES - 2>();
        __syncthreads();
        const int buf = kt % STAGES;
        if (kt + STAGES - 1 < NKT) issue(kt + STAGES - 1, (kt + STAGES - 1) % STAGES);
        else cp_commit();

#pragma unroll
        for (int ks = 0; ks < 2; ++ks) {
            const int kb = ks * 8;
            unsigned a[4][4], b[8][2];
#pragma unroll
            for (int mi = 0; mi < 4; mi++) {
                int r = m0 + mi * 16 + g;
                a[mi][0] = f2tf(As[buf][r][kb + t]);
                a[mi][1] = f2tf(As[buf][r + 8][kb + t]);
                a[mi][2] = f2tf(As[buf][r][kb + 4 + t]);
                a[mi][3] = f2tf(As[buf][r + 8][kb + 4 + t]);
            }
#pragma unroll
            for (int ni = 0; ni < 8; ni++) {
                int cn = n0 + ni * 8 + g;
                b[ni][0] = f2tf(Bs[buf][kb + t][cn]);
                b[ni][1] = f2tf(Bs[buf][kb + 4 + t][cn]);
            }
#pragma unroll
            for (int mi = 0; mi < 4; mi++)
#pragma unroll
                for (int ni = 0; ni < 8; ni++)
                    mma_tf32(acc[mi][ni], a[mi][0], a[mi][1], a[mi][2], a[mi][3],
                             b[ni][0], b[ni][1]);
        }
        __syncthreads();
    }

    const int rbase = blockIdx.y * 128 + m0;
    const int cbase = blockIdx.x * 128 + n0;
#pragma unroll
    for (int mi = 0; mi < 4; mi++) {
#pragma unroll
        for (int ni = 0; ni < 8; ni++) {
            int r = rbase + mi * 16 + g;
            int c = cbase + ni * 8 + 2 * t;
            float2 bb = *(const float2*)&bias[c];
            float2 v0 = { acc[mi][ni][0] + bb.x, acc[mi][ni][1] + bb.y };
            float2 v1 = { acc[mi][ni][2] + bb.x, acc[mi][ni][3] + bb.y };
            if (!scatter) {
                *(float2*)&C[(size_t)r * Dm + c]       = v0;
                *(float2*)&C[(size_t)(r + 8) * Dm + c] = v1;
            } else {
                int b0i = r >> 11, q0 = r & 2047;
                int h = c >> 6, d = c & 63;
                *(float2*)&C[((size_t)((b0i * Hh + h) * Sq) + q0) * Dk + d] = v0;
                int r1 = r + 8;
                int b1i = r1 >> 11, q1 = r1 & 2047;
                *(float2*)&C[((size_t)((b1i * Hh + h) * Sq) + q1) * Dk + d] = v1;
            }
        }
    }
}

// =============================================================================
// Final projection: out = Opre @ W_o + b_o (row-major), same GEMM shape.
// =============================================================================
__global__ void __launch_bounds__(128, 2) oproj_kernel(
    const float* __restrict__ A, const float* __restrict__ B,
    float* __restrict__ C, const float* __restrict__ bias)
{
    extern __shared__ float dsm[];
    float (*As)[128][20]  = (float(*)[128][20])dsm;
    float (*Bs)[16][136]  = (float(*)[16][136])(dsm + STAGES * 128 * 20);

    const int tid  = threadIdx.x;
    const int lane = tid & 31;
    const int wid  = tid >> 5;
    const int g = lane >> 2, t = lane & 3;
    const int m0 = (wid & 1) * 64;
    const int n0 = (wid >> 1) * 64;

    const float* Ab = A + (size_t)blockIdx.y * 128 * Dm;
    const float* Bb = B + blockIdx.x * 128;

    const int arow = tid >> 2;
    const int acol = (tid & 3) * 4;
    const int brow = tid >> 5;
    const int bcol = (tid & 31) * 4;

    const int NKT = Dm / 16;

    auto issue = [&](int kt, int st) {
#pragma unroll
        for (int i = 0; i < 4; i++)
            cp_async16(&As[st][arow + 32 * i][acol],
                       Ab + (size_t)(arow + 32 * i) * Dm + kt * 16 + acol);
#pragma unroll
        for (int i = 0; i < 4; i++)
            cp_async16(&Bs[st][brow + 4 * i][bcol],
                       Bb + (size_t)(kt * 16 + brow + 4 * i) * Dm + bcol);
        cp_commit();
    };

#pragma unroll
    for (int s = 0; s < STAGES - 1; ++s) issue(s, s);

    float acc[4][8][4];
#pragma unroll
    for (int mi = 0; mi < 4; mi++)
#pragma unroll
        for (int ni = 0; ni < 8; ni++)
#pragma unroll
            for (int r = 0; r < 4; r++) acc[mi][ni][r] = 0.f;

    for (int kt = 0; kt < NKT; ++kt) {
        cp_wait<STAGES - 2>();
        __syncthreads();
        const int buf = kt % STAGES;
        if (kt + STAGES - 1 < NKT) issue(kt + STAGES - 1, (kt + STAGES - 1) % STAGES);
        else cp_commit();

#pragma unroll
        for (int ks = 0; ks < 2; ++ks) {
            const int kb = ks * 8;
            unsigned a[4][4], b[8][2];
#pragma unroll
            for (int mi = 0; mi < 4; mi++) {
                int r = m0 + mi * 16 + g;
                a[mi][0] = f2tf(As[buf][r][kb + t]);
                a[mi][1] = f2tf(As[buf][r + 8][kb + t]);
                a[mi][2] = f2tf(As[buf][r][kb + 4 + t]);
                a[mi][3] = f2tf(As[buf][r + 8][kb + 4 + t]);
            }
#pragma unroll
            for (int ni = 0; ni < 8; ni++) {
                int cn = n0 + ni * 8 + g;
                b[ni][0] = f2tf(Bs[buf][kb + t][cn]);
                b[ni][1] = f2tf(Bs[buf][kb + 4 + t][cn]);
            }
#pragma unroll
            for (int mi = 0; mi < 4; mi++)
#pragma unroll
                for (int ni = 0; ni < 8; ni++)
                    mma_tf32(acc[mi][ni], a[mi][0], a[mi][1], a[mi][2], a[mi][3],
                             b[ni][0], b[ni][1]);
        }
        __syncthreads();
    }

    const int rbase = blockIdx.y * 128 + m0;
    const int cbase = blockIdx.x * 128 + n0;
#pragma unroll
    for (int mi = 0; mi < 4; mi++) {
#pragma unroll
        for (int ni = 0; ni < 8; ni++) {
            int r = rbase + mi * 16 + g;
            int c = cbase + ni * 8 + 2 * t;
            float2 bb = *(const float2*)&bias[c];
            float2 v0 = { acc[mi][ni][0] + bb.x, acc[mi][ni][1] + bb.y };
            float2 v1 = { acc[mi][ni][2] + bb.x, acc[mi][ni][3] + bb.y };
            *(float2*)&C[(size_t)r * Dm + c]       = v0;
            *(float2*)&C[(size_t)(r + 8) * Dm + c] = v1;
        }
    }
}

// =============================================================================
// Scores kernel: E = exp((Q@K^T)/8) per (b,h) + per-CTA row-sum partials.
// 256 thr, 8 warps (2m x 4n), warp tile 64x32, K=64 fully staged.
// Epilogue: fragments -> smem tile -> fully-coalesced float4 row streaming,
// exp applied on the way out, row sums via one warp-reduce per row.
// =============================================================================
__global__ void __launch_bounds__(256, 2) scores_tc_kernel(
    const float* __restrict__ Q, const float* __restrict__ K,
    float* __restrict__ E, float* __restrict__ Zp)
{
    extern __shared__ unsigned dynsmem[];
    unsigned (*Qs)[68] = (unsigned(*)[68])dynsmem;
    unsigned (*Ks)[68] = (unsigned(*)[68])(dynsmem + 128 * 68);

    const int tid  = threadIdx.x;
    const int lane = tid & 31;
    const int wid  = tid >> 5;
    const int g = lane >> 2, t = lane & 3;
    const int m0 = (wid & 1) * 64;
    const int n0 = (wid >> 1) * 32;

    const float* Qb = Q + (size_t)blockIdx.z * Sq * Dk + (size_t)blockIdx.y * 128 * Dk;
    const float* Kb = K + (size_t)blockIdx.z * Sq * Dk + (size_t)blockIdx.x * 128 * Dk;

#pragma unroll
    for (int i = 0; i < 8; ++i) {
        int idx = i * 256 + tid;
        int row = idx >> 4;
        int c4  = (idx & 15) * 4;
        float4 q = *(const float4*)&Qb[(size_t)row * Dk + c4];
        uint4 uq = { f2tf(q.x), f2tf(q.y), f2tf(q.z), f2tf(q.w) };
        *(uint4*)&Qs[row][c4] = uq;
        float4 k = *(const float4*)&Kb[(size_t)row * Dk + c4];
        uint4 uk = { f2tf(k.x), f2tf(k.y), f2tf(k.z), f2tf(k.w) };
        *(uint4*)&Ks[row][c4] = uk;
    }
    __syncthreads();

    float acc[4][4][4];
#pragma unroll
    for (int mi = 0; mi < 4; mi++)
#pragma unroll
        for (int ni = 0; ni < 4; ni++)
#pragma unroll
            for (int r = 0; r < 4; r++) acc[mi][ni][r] = 0.f;

#pragma unroll
    for (int ks = 0; ks < 8; ++ks) {
        const int kb = ks * 8;
        unsigned a[4][4], b[4][2];
#pragma unroll
        for (int mi = 0; mi < 4; mi++) {
            int r = m0 + mi * 16 + g;
            a[mi][0] = Qs[r][kb + t];
            a[mi][1] = Qs[r + 8][kb + t];
            a[mi][2] = Qs[r][kb + 4 + t];
            a[mi][3] = Qs[r + 8][kb + 4 + t];
        }
#pragma unroll
        for (int ni = 0; ni < 4; ni++) {
            int cn = n0 + ni * 8 + g;
            b[ni][0] = Ks[cn][kb + t];
            b[ni][1] = Ks[cn][kb + 4 + t];
        }
#pragma unroll
        for (int mi = 0; mi < 4; mi++)
#pragma unroll
            for (int ni = 0; ni < 4; ni++)
                mma_tf32(acc[mi][ni], a[mi][0], a[mi][1], a[mi][2], a[mi][3],
                         b[ni][0], b[ni][1]);
    }

    // ---- stage fragments into smem tile (reuse Qs/Ks space) ----
    __syncthreads();
    float (*Et)[132] = (float(*)[132])dynsmem;   // 128x132 floats = 67584 B
#pragma unroll
    for (int mi = 0; mi < 4; mi++) {
        int r = m0 + mi * 16 + g;
#pragma unroll
        for (int ni = 0; ni < 4; ni++) {
            int c = n0 + ni * 8 + 2 * t;
            float2 v0 = { acc[mi][ni][0], acc[mi][ni][1] };
            float2 v1 = { acc[mi][ni][2], acc[mi][ni][3] };
            *(float2*)&Et[r][c]     = v0;
            *(float2*)&Et[r + 8][c] = v1;
        }
    }
    __syncthreads();

    // ---- stream out: warp w handles rows w, w+8, ..., fully coalesced ----
    float* Eb = E + (size_t)blockIdx.z * Sq * Sq;
    const int rbase = blockIdx.y * 128;
    const int cbase = blockIdx.x * 128;
    float myzp = 0.f;
#pragma unroll
    for (int i = 0; i < 16; ++i) {
        int row = i * 8 + wid;
        float4 v = *(const float4*)&Et[row][lane * 4];
        float e0 = __expf(v.x * 0.125f);
        float e1 = __expf(v.y * 0.125f);
        float e2 = __expf(v.z * 0.125f);
        float e3 = __expf(v.w * 0.125f);
        float4 o = { e0, e1, e2, e3 };
        *(float4*)&Eb[(size_t)(rbase + row) * Sq + cbase + lane * 4] = o;
        float s = warp_sum((e0 + e1) + (e2 + e3));
        if (lane == i) myzp = s;
    }
    if (lane < 16) {
        int row = lane * 8 + wid;
        Zp[(size_t)blockIdx.x * NROWS + (size_t)blockIdx.z * Sq + rbase + row] = myzp;
    }
}

// =============================================================================
// Z reduce: RZ[row] = 0.25 / sum_x Zp[x][row]  (fixed order -> deterministic)
// =============================================================================
__global__ void __launch_bounds__(256) zred_kernel(
    const float* __restrict__ Zp, float* __restrict__ RZ)
{
    int i = blockIdx.x * 256 + threadIdx.x;
    float s = 0.f;
#pragma unroll
    for (int x = 0; x < NXT; x++) s += Zp[(size_t)x * NROWS + i];
    RZ[i] = 0.25f / s;
}

// =============================================================================
// Fused avg + avg@V: per batch, block tile 128(q) x 256(full Dm), BK=16.
// =============================================================================
#define AV_RZ 0
#define AV_AS 512
#define AV_BS (512 + 2*128*20)
#define AV_SMEM_FLOATS (512 + 2*128*20 + 2*16*264)

__global__ void __launch_bounds__(256, 1) avgv_fused_kernel(
    const float* __restrict__ E, const float* __restrict__ RZ,
    const float* __restrict__ V, float* __restrict__ avg,
    float* __restrict__ Opre)
{
    extern __shared__ float sm[];
    float* rzs = sm + AV_RZ;
    float (*As)[128][20]  = (float(*)[128][20])(sm + AV_AS);
    float (*Bs)[16][264]  = (float(*)[16][264])(sm + AV_BS);

    const int tid  = threadIdx.x;
    const int lane = tid & 31;
    const int wid  = tid >> 5;
    const int g = lane >> 2, t = lane & 3;
    const int m0 = (wid & 1) * 64;
    const int n0 = (wid >> 1) * 64;

    const int b  = blockIdx.z;
    const int qb = blockIdx.y * 128;

    const float* Ep[Hh];
#pragma unroll
    for (int h = 0; h < Hh; h++)
        Ep[h] = E + ((size_t)(b * Hh + h) * Sq + qb) * Sq;
    const float* Vb = V + (size_t)b * Sq * Dm;
    float* avgb = avg + ((size_t)b * Sq + qb) * Sq;

    for (int i = tid; i < 512; i += 256) {
        int h = i & 3, row = i >> 2;
        rzs[row * 4 + h] = RZ[(size_t)(b * Hh + h) * Sq + qb + row];
    }

    const int arow = tid >> 2;
    const int acol = (tid & 3) * 4;
    const int brow = tid >> 4;
    const int bcolb = (tid & 15) * 4;

    float4 pa[Hh][2];

    auto loadA = [&](int kt) {
#pragma unroll
        for (int h = 0; h < Hh; h++) {
            pa[h][0] = *(const float4*)&Ep[h][(size_t)arow * Sq + kt * 16 + acol];
            pa[h][1] = *(const float4*)&Ep[h][(size_t)(arow + 64) * Sq + kt * 16 + acol];
        }
    };
    auto issueB = [&](int kt, int buf) {
#pragma unroll
        for (int j = 0; j < 4; j++)
            cp_async16(&Bs[buf][brow][bcolb + j * 64],
                       Vb + (size_t)(kt * 16 + brow) * Dm + bcolb + j * 64);
        cp_commit();
    };
    auto storeA = [&](int buf, int kt) {
        float rz0[Hh], rz1[Hh];
#pragma unroll
        for (int h = 0; h < Hh; h++) {
            rz0[h] = rzs[arow * 4 + h];
            rz1[h] = rzs[(arow + 64) * 4 + h];
        }
        float4 c0 = {0,0,0,0}, c1 = {0,0,0,0};
#pragma unroll
        for (int h = 0; h < Hh; h++) {
            c0.x += pa[h][0].x * rz0[h]; c0.y += pa[h][0].y * rz0[h];
            c0.z += pa[h][0].z * rz0[h]; c0.w += pa[h][0].w * rz0[h];
            c1.x += pa[h][1].x * rz1[h]; c1.y += pa[h][1].y * rz1[h];
            c1.z += pa[h][1].z * rz1[h]; c1.w += pa[h][1].w * rz1[h];
        }
        *(float4*)&avgb[(size_t)arow * Sq + kt * 16 + acol]        = c0;
        *(float4*)&avgb[(size_t)(arow + 64) * Sq + kt * 16 + acol] = c1;
        *(float4*)&As[buf][arow][acol]      = c0;
        *(float4*)&As[buf][arow + 64][acol] = c1;
    };

    float acc[4][8][4];
#pragma unroll
    for (int mi = 0; mi < 4; mi++)
#pragma unroll
        for (int ni = 0; ni < 8; ni++)
#pragma unroll
            for (int r = 0; r < 4; r++) acc[mi][ni][r] = 0.f;

    loadA(0);
    issueB(0, 0);
    __syncthreads();
    storeA(0, 0);
    cp_wait<0>();
    __syncthreads();

    const int NKT = Sq / 16;
    for (int kt = 0; kt < NKT; ++kt) {
        const int buf = kt & 1;
        if (kt + 1 < NKT) {
            loadA(kt + 1);
            issueB(kt + 1, buf ^ 1);
        }

#pragma unroll
        for (int ks = 0; ks < 2; ++ks) {
            const int kb = ks * 8;
            unsigned a[4][4], bb[8][2];
#pragma unroll
            for (int mi = 0; mi < 4; mi++) {
                int r = m0 + mi * 16 + g;
                a[mi][0] = f2tf(As[buf][r][kb + t]);
                a[mi][1] = f2tf(As[buf][r + 8][kb + t]);
                a[mi][2] = f2tf(As[buf][r][kb + 4 + t]);
                a[mi][3] = f2tf(As[buf][r + 8][kb + 4 + t]);
            }
#pragma unroll
            for (int ni = 0; ni < 8; ni++) {
                int cn = n0 + ni * 8 + g;
                bb[ni][0] = f2tf(Bs[buf][kb + t][cn]);
                bb[ni][1] = f2tf(Bs[buf][kb + 4 + t][cn]);
            }
#pragma unroll
            for (int mi = 0; mi < 4; mi++)
#pragma unroll
                for (int ni = 0; ni < 8; ni++)
                    mma_tf32(acc[mi][ni], a[mi][0], a[mi][1], a[mi][2], a[mi][3],
                             bb[ni][0], bb[ni][1]);
        }

        if (kt + 1 < NKT) {
            storeA(buf ^ 1, kt + 1);
            cp_wait<0>();
        }
        __syncthreads();
    }

    float* Ob = Opre + (size_t)b * Sq * Dm;
    const int rbase = qb + m0;
    const int cbase = n0;
#pragma unroll
    for (int mi = 0; mi < 4; mi++) {
#pragma unroll
        for (int ni = 0; ni < 8; ni++) {
            int r = rbase + mi * 16 + g;
            int c = cbase + ni * 8 + 2 * t;
            float2 v0 = { acc[mi][ni][0], acc[mi][ni][1] };
            float2 v1 = { acc[mi][ni][2], acc[mi][ni][3] };
            *(float2*)&Ob[(size_t)r * Dm + c]       = v0;
            *(float2*)&Ob[(size_t)(r + 8) * Dm + c] = v1;
        }
    }
}

// =============================================================================
// Launch
// =============================================================================
extern "C" void kernel_launch(void* const* d_in, const int* in_sizes, int n_in,
                              void* d_out, int out_size)
{
    (void)in_sizes; (void)n_in; (void)out_size;
    const float* query = (const float*)d_in[0];
    const float* key   = (const float*)d_in[1];
    const float* value = (const float*)d_in[2];
    const float* W_q   = (const float*)d_in[3];
    const float* b_q   = (const float*)d_in[4];
    const float* W_k   = (const float*)d_in[5];
    const float* b_k   = (const float*)d_in[6];
    const float* W_v   = (const float*)d_in[7];
    const float* b_v   = (const float*)d_in[8];
    const float* W_o   = (const float*)d_in[9];
    const float* b_o   = (const float*)d_in[10];

    float* out = (float*)d_out;                 // (B,S,D)
    float* avg = out + OUT0_ELEMS;              // (B,S,S)

    float *pQ, *pK, *pV, *pE, *pO, *pZp, *pRZ;
    cudaGetSymbolAddress((void**)&pQ,  g_Q);
    cudaGetSymbolAddress((void**)&pK,  g_K);
    cudaGetSymbolAddress((void**)&pV,  g_V);
    cudaGetSymbolAddress((void**)&pE,  g_E);
    cudaGetSymbolAddress((void**)&pO,  g_O);
    cudaGetSymbolAddress((void**)&pZp, g_Zp);
    cudaGetSymbolAddress((void**)&pRZ, g_RZ);

    const int gemm_smem = (STAGES * 128 * 20 + STAGES * 16 * 136) * 4;
    cudaFuncSetAttribute(qkv_proj_kernel,
        cudaFuncAttributeMaxDynamicSharedMemorySize, gemm_smem);
    cudaFuncSetAttribute(oproj_kernel,
        cudaFuncAttributeMaxDynamicSharedMemorySize, gemm_smem);

    // 1: fused Q/K/V projections (one launch, 768 CTAs)
    {
        dim3 grid(Dm / 128, NTOK / 128, 3);
        qkv_proj_kernel<<<grid, 128, gemm_smem>>>(
            query, key, value, W_q, W_k, W_v, b_q, b_k, b_v, pQ, pK, pV);
    }

    // 2: E = exp(Q@K^T / 8) + row-sum partials
    {
        const int smem = 2 * 128 * 68 * 4;   // 69632 B (also fits 128x132 floats)
        cudaFuncSetAttribute(scores_tc_kernel,
            cudaFuncAttributeMaxDynamicSharedMemorySize, smem);
        dim3 grid(Sq / 128, Sq / 128, Bsz * Hh);
        scores_tc_kernel<<<grid, 256, smem>>>(pQ, pK, pE, pZp);
    }

    // 3: deterministic Z reduce -> 0.25/Z
    zred_kernel<<<NROWS / 256, 256>>>(pZp, pRZ);

    // 4: fused avg_attn production + avg@V
    {
        const int smem = AV_SMEM_FLOATS * 4;  // 56320 B
        cudaFuncSetAttribute(avgv_fused_kernel,
            cudaFuncAttributeMaxDynamicSharedMemorySize, smem);
        dim3 grid(1, Sq / 128, Bsz);
        avgv_fused_kernel<<<grid, 256, smem>>>(pE, pRZ, pV, avg, pO);
    }

    // 5: final projection out = Opre @ W_o + b_o
    {
        dim3 grid(Dm / 128, NTOK / 128, 1);
        oproj_kernel<<<grid, 128, gemm_smem>>>(pO, W_o, out, b_o);
    }
}

// round 6
// speedup vs baseline: 1.0304x; 1.0304x over previous
#include <cuda_runtime.h>
#include <math.h>

// Problem constants
#define Bsz 8
#define Sq  2048
#define Dm  256
#define Hh  4
#define Dk  64
#define NTOK (Bsz*Sq)          // 16384
#define OUT0_ELEMS ((size_t)NTOK*Dm) // 4194304
#define NROWS (Bsz*Hh*Sq)      // 65536 (b,h,q) rows
#define NXT 16                 // k-tiles per score row (2048/128)

// ---------------- scratch (static device globals; allocation-free contract) ---
__device__ float g_Q[(size_t)Bsz*Hh*Sq*Dk];   // (b,h,q,d) 16MB
__device__ float g_K[(size_t)Bsz*Hh*Sq*Dk];   // 16MB
__device__ float g_V[(size_t)NTOK*Dm];        // 16MB
__device__ float g_E[(size_t)Bsz*Hh*Sq*Sq];   // exp(scores), 512MiB
__device__ float g_O[(size_t)NTOK*Dm];        // attn output pre-proj, 16MB
__device__ float g_Zp[(size_t)NXT*NROWS];     // per-k-tile row-sum partials, 4MB
__device__ float g_RZ[(size_t)NROWS];         // 0.25 / rowsum

// =============================================================================
// helpers
// =============================================================================
__device__ __forceinline__ unsigned f2tf(float f) {
    unsigned u;
    asm("cvt.rna.tf32.f32 %0, %1;" : "=r"(u) : "f"(f));
    return u;
}
__device__ __forceinline__ void mma_tf32(float c[4],
    unsigned a0, unsigned a1, unsigned a2, unsigned a3,
    unsigned b0, unsigned b1)
{
    asm volatile(
        "mma.sync.aligned.m16n8k8.row.col.f32.tf32.tf32.f32 "
        "{%0,%1,%2,%3},{%4,%5,%6,%7},{%8,%9},{%0,%1,%2,%3};"
        : "+f"(c[0]), "+f"(c[1]), "+f"(c[2]), "+f"(c[3])
        : "r"(a0), "r"(a1), "r"(a2), "r"(a3), "r"(b0), "r"(b1));
}
__device__ __forceinline__ void cp_async16(void* smem, const void* gmem) {
    unsigned saddr = (unsigned)__cvta_generic_to_shared(smem);
    asm volatile("cp.async.cg.shared.global [%0], [%1], 16;\n"
                 :: "r"(saddr), "l"(gmem));
}
__device__ __forceinline__ void cp_commit() {
    asm volatile("cp.async.commit_group;\n");
}
template<int N>
__device__ __forceinline__ void cp_wait() {
    asm volatile("cp.async.wait_group %0;\n" :: "n"(N));
}

#define STAGES 4

// =============================================================================
// Fused QKV projection: one launch, grid.z in {0,1,2} selects operands.
// z<2 scatters head-major (Q,K); z==2 row-major (V). 128x128 block, 4 warps,
// 64x64 warp tile, BK=16, 4-stage cp.async. K=Dm=256.
// =============================================================================
__global__ void __launch_bounds__(128, 2) qkv_proj_kernel(
    const float* __restrict__ q, const float* __restrict__ k, const float* __restrict__ v,
    const float* __restrict__ Wq, const float* __restrict__ Wk, const float* __restrict__ Wv,
    const float* __restrict__ bq, const float* __restrict__ bk, const float* __restrict__ bv,
    float* __restrict__ Cq, float* __restrict__ Ck, float* __restrict__ Cv)
{
    extern __shared__ float dsm[];
    float (*As)[128][20]  = (float(*)[128][20])dsm;
    float (*Bs)[16][136]  = (float(*)[16][136])(dsm + STAGES * 128 * 20);

    const int sel = blockIdx.z;
    const float* A    = sel == 0 ? q  : sel == 1 ? k  : v;
    const float* B    = sel == 0 ? Wq : sel == 1 ? Wk : Wv;
    const float* bias = sel == 0 ? bq : sel == 1 ? bk : bv;
    float*       C    = sel == 0 ? Cq : sel == 1 ? Ck : Cv;
    const bool scatter = sel < 2;

    const int tid  = threadIdx.x;
    const int lane = tid & 31;
    const int wid  = tid >> 5;
    const int g = lane >> 2, t = lane & 3;
    const int m0 = (wid & 1) * 64;
    const int n0 = (wid >> 1) * 64;

    const float* Ab = A + (size_t)blockIdx.y * 128 * Dm;
    const float* Bb = B + blockIdx.x * 128;

    const int arow = tid >> 2;
    const int acol = (tid & 3) * 4;
    const int brow = tid >> 5;
    const int bcol = (tid & 31) * 4;

    const int NKT = Dm / 16;   // 16

    auto issue = [&](int kt, int st) {
#pragma unroll
        for (int i = 0; i < 4; i++)
            cp_async16(&As[st][arow + 32 * i][acol],
                       Ab + (size_t)(arow + 32 * i) * Dm + kt * 16 + acol);
#pragma unroll
        for (int i = 0; i < 4; i++)
            cp_async16(&Bs[st][brow + 4 * i][bcol],
                       Bb + (size_t)(kt * 16 + brow + 4 * i) * Dm + bcol);
        cp_commit();
    };

#pragma unroll
    for (int s = 0; s < STAGES - 1; ++s) issue(s, s);

    float acc[4][8][4];
#pragma unroll
    for (int mi = 0; mi < 4; mi++)
#pragma unroll
        for (int ni = 0; ni < 8; ni++)
#pragma unroll
            for (int r = 0; r < 4; r++) acc[mi][ni][r] = 0.f;

    for (int kt = 0; kt < NKT; ++kt) {
        cp_wait<STAGES - 2>();
        __syncthreads();
        const int buf = kt % STAGES;
        if (kt + STAGES - 1 < NKT) issue(kt + STAGES - 1, (kt + STAGES - 1) % STAGES);
        else cp_commit();

#pragma unroll
        for (int ks = 0; ks < 2; ++ks) {
            const int kb = ks * 8;
            unsigned a[4][4], b[8][2];
#pragma unroll
            for (int mi = 0; mi < 4; mi++) {
                int r = m0 + mi * 16 + g;
                a[mi][0] = f2tf(As[buf][r][kb + t]);
                a[mi][1] = f2tf(As[buf][r + 8][kb + t]);
                a[mi][2] = f2tf(As[buf][r][kb + 4 + t]);
                a[mi][3] = f2tf(As[buf][r + 8][kb + 4 + t]);
            }
#pragma unroll
            for (int ni = 0; ni < 8; ni++) {
                int cn = n0 + ni * 8 + g;
                b[ni][0] = f2tf(Bs[buf][kb + t][cn]);
                b[ni][1] = f2tf(Bs[buf][kb + 4 + t][cn]);
            }
#pragma unroll
            for (int mi = 0; mi < 4; mi++)
#pragma unroll
                for (int ni = 0; ni < 8; ni++)
                    mma_tf32(acc[mi][ni], a[mi][0], a[mi][1], a[mi][2], a[mi][3],
                             b[ni][0], b[ni][1]);
        }
        __syncthreads();
    }

    const int rbase = blockIdx.y * 128 + m0;
    const int cbase = blockIdx.x * 128 + n0;
#pragma unroll
    for (int mi = 0; mi < 4; mi++) {
#pragma unroll
        for (int ni = 0; ni < 8; ni++) {
            int r = rbase + mi * 16 + g;
            int c = cbase + ni * 8 + 2 * t;
            float2 bb = *(const float2*)&bias[c];
            float2 v0 = { acc[mi][ni][0] + bb.x, acc[mi][ni][1] + bb.y };
            float2 v1 = { acc[mi][ni][2] + bb.x, acc[mi][ni][3] + bb.y };
            if (!scatter) {
                *(float2*)&C[(size_t)r * Dm + c]       = v0;
                *(float2*)&C[(size_t)(r + 8) * Dm + c] = v1;
            } else {
                int b0i = r >> 11, q0 = r & 2047;
                int h = c >> 6, d = c & 63;
                *(float2*)&C[((size_t)((b0i * Hh + h) * Sq) + q0) * Dk + d] = v0;
                int r1 = r + 8;
                int b1i = r1 >> 11, q1 = r1 & 2047;
                *(float2*)&C[((size_t)((b1i * Hh + h) * Sq) + q1) * Dk + d] = v1;
            }
        }
    }
}

// =============================================================================
// Final projection: out = Opre @ W_o + b_o
// =============================================================================
__global__ void __launch_bounds__(128, 2) oproj_kernel(
    const float* __restrict__ A, const float* __restrict__ B,
    float* __restrict__ C, const float* __restrict__ bias)
{
    extern __shared__ float dsm[];
    float (*As)[128][20]  = (float(*)[128][20])dsm;
    float (*Bs)[16][136]  = (float(*)[16][136])(dsm + STAGES * 128 * 20);

    const int tid  = threadIdx.x;
    const int lane = tid & 31;
    const int wid  = tid >> 5;
    const int g = lane >> 2, t = lane & 3;
    const int m0 = (wid & 1) * 64;
    const int n0 = (wid >> 1) * 64;

    const float* Ab = A + (size_t)blockIdx.y * 128 * Dm;
    const float* Bb = B + blockIdx.x * 128;

    const int arow = tid >> 2;
    const int acol = (tid & 3) * 4;
    const int brow = tid >> 5;
    const int bcol = (tid & 31) * 4;

    const int NKT = Dm / 16;

    auto issue = [&](int kt, int st) {
#pragma unroll
        for (int i = 0; i < 4; i++)
            cp_async16(&As[st][arow + 32 * i][acol],
                       Ab + (size_t)(arow + 32 * i) * Dm + kt * 16 + acol);
#pragma unroll
        for (int i = 0; i < 4; i++)
            cp_async16(&Bs[st][brow + 4 * i][bcol],
                       Bb + (size_t)(kt * 16 + brow + 4 * i) * Dm + bcol);
        cp_commit();
    };

#pragma unroll
    for (int s = 0; s < STAGES - 1; ++s) issue(s, s);

    float acc[4][8][4];
#pragma unroll
    for (int mi = 0; mi < 4; mi++)
#pragma unroll
        for (int ni = 0; ni < 8; ni++)
#pragma unroll
            for (int r = 0; r < 4; r++) acc[mi][ni][r] = 0.f;

    for (int kt = 0; kt < NKT; ++kt) {
        cp_wait<STAGES - 2>();
        __syncthreads();
        const int buf = kt % STAGES;
        if (kt + STAGES - 1 < NKT) issue(kt + STAGES - 1, (kt + STAGES - 1) % STAGES);
        else cp_commit();

#pragma unroll
        for (int ks = 0; ks < 2; ++ks) {
            const int kb = ks * 8;
            unsigned a[4][4], b[8][2];
#pragma unroll
            for (int mi = 0; mi < 4; mi++) {
                int r = m0 + mi * 16 + g;
                a[mi][0] = f2tf(As[buf][r][kb + t]);
                a[mi][1] = f2tf(As[buf][r + 8][kb + t]);
                a[mi][2] = f2tf(As[buf][r][kb + 4 + t]);
                a[mi][3] = f2tf(As[buf][r + 8][kb + 4 + t]);
            }
#pragma unroll
            for (int ni = 0; ni < 8; ni++) {
                int cn = n0 + ni * 8 + g;
                b[ni][0] = f2tf(Bs[buf][kb + t][cn]);
                b[ni][1] = f2tf(Bs[buf][kb + 4 + t][cn]);
            }
#pragma unroll
            for (int mi = 0; mi < 4; mi++)
#pragma unroll
                for (int ni = 0; ni < 8; ni++)
                    mma_tf32(acc[mi][ni], a[mi][0], a[mi][1], a[mi][2], a[mi][3],
                             b[ni][0], b[ni][1]);
        }
        __syncthreads();
    }

    const int rbase = blockIdx.y * 128 + m0;
    const int cbase = blockIdx.x * 128 + n0;
#pragma unroll
    for (int mi = 0; mi < 4; mi++) {
#pragma unroll
        for (int ni = 0; ni < 8; ni++) {
            int r = rbase + mi * 16 + g;
            int c = cbase + ni * 8 + 2 * t;
            float2 bb = *(const float2*)&bias[c];
            float2 v0 = { acc[mi][ni][0] + bb.x, acc[mi][ni][1] + bb.y };
            float2 v1 = { acc[mi][ni][2] + bb.x, acc[mi][ni][3] + bb.y };
            *(float2*)&C[(size_t)r * Dm + c]       = v0;
            *(float2*)&C[(size_t)(r + 8) * Dm + c] = v1;
        }
    }
}

// =============================================================================
// Scores kernel (R4 epilogue): E = exp((Q@K^T)/8) + per-CTA row-sum partials.
// 256 thr, 8 warps (2m x 4n), warp tile 64x32, K=64 fully staged.
// =============================================================================
__global__ void __launch_bounds__(256, 2) scores_tc_kernel(
    const float* __restrict__ Q, const float* __restrict__ K,
    float* __restrict__ E, float* __restrict__ Zp)
{
    extern __shared__ unsigned dynsmem[];
    unsigned (*Qs)[68] = (unsigned(*)[68])dynsmem;
    unsigned (*Ks)[68] = (unsigned(*)[68])(dynsmem + 128 * 68);
    __shared__ float wsum[4][128];

    const int tid  = threadIdx.x;
    const int lane = tid & 31;
    const int wid  = tid >> 5;
    const int g = lane >> 2, t = lane & 3;
    const int m0 = (wid & 1) * 64;
    const int n0 = (wid >> 1) * 32;
    const int nwid = wid >> 1;

    const float* Qb = Q + (size_t)blockIdx.z * Sq * Dk + (size_t)blockIdx.y * 128 * Dk;
    const float* Kb = K + (size_t)blockIdx.z * Sq * Dk + (size_t)blockIdx.x * 128 * Dk;

#pragma unroll
    for (int i = 0; i < 8; ++i) {
        int idx = i * 256 + tid;
        int row = idx >> 4;
        int c4  = (idx & 15) * 4;
        float4 q = *(const float4*)&Qb[(size_t)row * Dk + c4];
        uint4 uq = { f2tf(q.x), f2tf(q.y), f2tf(q.z), f2tf(q.w) };
        *(uint4*)&Qs[row][c4] = uq;
        float4 k = *(const float4*)&Kb[(size_t)row * Dk + c4];
        uint4 uk = { f2tf(k.x), f2tf(k.y), f2tf(k.z), f2tf(k.w) };
        *(uint4*)&Ks[row][c4] = uk;
    }
    __syncthreads();

    float acc[4][4][4];
#pragma unroll
    for (int mi = 0; mi < 4; mi++)
#pragma unroll
        for (int ni = 0; ni < 4; ni++)
#pragma unroll
            for (int r = 0; r < 4; r++) acc[mi][ni][r] = 0.f;

#pragma unroll
    for (int ks = 0; ks < 8; ++ks) {
        const int kb = ks * 8;
        unsigned a[4][4], b[4][2];
#pragma unroll
        for (int mi = 0; mi < 4; mi++) {
            int r = m0 + mi * 16 + g;
            a[mi][0] = Qs[r][kb + t];
            a[mi][1] = Qs[r + 8][kb + t];
            a[mi][2] = Qs[r][kb + 4 + t];
            a[mi][3] = Qs[r + 8][kb + 4 + t];
        }
#pragma unroll
        for (int ni = 0; ni < 4; ni++) {
            int cn = n0 + ni * 8 + g;
            b[ni][0] = Ks[cn][kb + t];
            b[ni][1] = Ks[cn][kb + 4 + t];
        }
#pragma unroll
        for (int mi = 0; mi < 4; mi++)
#pragma unroll
            for (int ni = 0; ni < 4; ni++)
                mma_tf32(acc[mi][ni], a[mi][0], a[mi][1], a[mi][2], a[mi][3],
                         b[ni][0], b[ni][1]);
    }

    float* Eb = E + (size_t)blockIdx.z * Sq * Sq;
    const int rbase = blockIdx.y * 128 + m0;
    const int cbase = blockIdx.x * 128 + n0;
#pragma unroll
    for (int mi = 0; mi < 4; mi++) {
        float s0 = 0.f, s1 = 0.f;
        int r = rbase + mi * 16 + g;
#pragma unroll
        for (int ni = 0; ni < 4; ni++) {
            int c = cbase + ni * 8 + 2 * t;
            float e00 = __expf(acc[mi][ni][0] * 0.125f);
            float e01 = __expf(acc[mi][ni][1] * 0.125f);
            float e10 = __expf(acc[mi][ni][2] * 0.125f);
            float e11 = __expf(acc[mi][ni][3] * 0.125f);
            float2 v0 = { e00, e01 };
            float2 v1 = { e10, e11 };
            *(float2*)&Eb[(size_t)r * Sq + c]       = v0;
            *(float2*)&Eb[(size_t)(r + 8) * Sq + c] = v1;
            s0 += e00 + e01;
            s1 += e10 + e11;
        }
        s0 += __shfl_xor_sync(0xffffffffu, s0, 1);
        s0 += __shfl_xor_sync(0xffffffffu, s0, 2);
        s1 += __shfl_xor_sync(0xffffffffu, s1, 1);
        s1 += __shfl_xor_sync(0xffffffffu, s1, 2);
        if (t == 0) {
            wsum[nwid][m0 + mi * 16 + g]     = s0;
            wsum[nwid][m0 + mi * 16 + g + 8] = s1;
        }
    }
    __syncthreads();
    if (tid < 128) {
        float zp = (wsum[0][tid] + wsum[1][tid]) + (wsum[2][tid] + wsum[3][tid]);
        Zp[(size_t)blockIdx.x * NROWS + (size_t)blockIdx.z * Sq
           + blockIdx.y * 128 + tid] = zp;
    }
}

// =============================================================================
// Z reduce: RZ[row] = 0.25 / sum_x Zp[x][row]
// =============================================================================
__global__ void __launch_bounds__(256) zred_kernel(
    const float* __restrict__ Zp, float* __restrict__ RZ)
{
    int i = blockIdx.x * 256 + threadIdx.x;
    float s = 0.f;
#pragma unroll
    for (int x = 0; x < NXT; x++) s += Zp[(size_t)x * NROWS + i];
    RZ[i] = 0.25f / s;
}

// =============================================================================
// Fused avg + avg@V: block tile 64(q) x 256(Dm), BK=16, double buffered.
// 256 thr, 8 warps (2m x 4n), warp tile 32x64, occupancy 2 (grid 256 CTAs).
// smem (floats): rzs[64*4] | As[2][64][20] | Bs[2][16][264]
// =============================================================================
#define AV_RZ 0
#define AV_AS 256
#define AV_BS (256 + 2*64*20)
#define AV_SMEM_FLOATS (256 + 2*64*20 + 2*16*264)

__global__ void __launch_bounds__(256, 2) avgv_fused_kernel(
    const float* __restrict__ E, const float* __restrict__ RZ,
    const float* __restrict__ V, float* __restrict__ avg,
    float* __restrict__ Opre)
{
    extern __shared__ float sm[];
    float* rzs = sm + AV_RZ;                      // [row][h] : row*4+h
    float (*As)[64][20]   = (float(*)[64][20])(sm + AV_AS);
    float (*Bs)[16][264]  = (float(*)[16][264])(sm + AV_BS);

    const int tid  = threadIdx.x;
    const int lane = tid & 31;
    const int wid  = tid >> 5;
    const int g = lane >> 2, t = lane & 3;
    const int m0 = (wid & 1) * 32;
    const int n0 = (wid >> 1) * 64;

    const int b  = blockIdx.z;
    const int qb = blockIdx.y * 64;

    const float* Ep[Hh];
#pragma unroll
    for (int h = 0; h < Hh; h++)
        Ep[h] = E + ((size_t)(b * Hh + h) * Sq + qb) * Sq;
    const float* Vb = V + (size_t)b * Sq * Dm;
    float* avgb = avg + ((size_t)b * Sq + qb) * Sq;

    // rz staging (64 rows x 4 heads)
    if (tid < 256) {
        int h = tid & 3, row = tid >> 2;
        if (row < 64)
            rzs[row * 4 + h] = RZ[(size_t)(b * Hh + h) * Sq + qb + row];
    }

    const int arow  = tid >> 2;          // 0..63
    const int acol  = (tid & 3) * 4;     // 0,4,8,12
    const int brow  = tid >> 4;          // 0..15
    const int bcolb = (tid & 15) * 4;

    float4 pa[Hh];

    auto loadA = [&](int kt) {
#pragma unroll
        for (int h = 0; h < Hh; h++)
            pa[h] = *(const float4*)&Ep[h][(size_t)arow * Sq + kt * 16 + acol];
    };
    auto issueB = [&](int kt, int buf) {
#pragma unroll
        for (int j = 0; j < 4; j++)
            cp_async16(&Bs[buf][brow][bcolb + j * 64],
                       Vb + (size_t)(kt * 16 + brow) * Dm + bcolb + j * 64);
        cp_commit();
    };
    auto storeA = [&](int buf, int kt) {
        float4 c0 = {0,0,0,0};
#pragma unroll
        for (int h = 0; h < Hh; h++) {
            float rz = rzs[arow * 4 + h];
            c0.x += pa[h].x * rz; c0.y += pa[h].y * rz;
            c0.z += pa[h].z * rz; c0.w += pa[h].w * rz;
        }
        *(float4*)&avgb[(size_t)arow * Sq + kt * 16 + acol] = c0;
        *(float4*)&As[buf][arow][acol] = c0;
    };

    float acc[2][8][4];
#pragma unroll
    for (int mi = 0; mi < 2; mi++)
#pragma unroll
        for (int ni = 0; ni < 8; ni++)
#pragma unroll
            for (int r = 0; r < 4; r++) acc[mi][ni][r] = 0.f;

    loadA(0);
    issueB(0, 0);
    __syncthreads();            // rzs visible
    storeA(0, 0);
    cp_wait<0>();
    __syncthreads();

    const int NKT = Sq / 16;    // 128
    for (int kt = 0; kt < NKT; ++kt) {
        const int buf = kt & 1;
        if (kt + 1 < NKT) {
            loadA(kt + 1);
            issueB(kt + 1, buf ^ 1);
        }

#pragma unroll
        for (int ks = 0; ks < 2; ++ks) {
            const int kb = ks * 8;
            unsigned a[2][4], bb[8][2];
#pragma unroll
            for (int mi = 0; mi < 2; mi++) {
                int r = m0 + mi * 16 + g;
                a[mi][0] = f2tf(As[buf][r][kb + t]);
                a[mi][1] = f2tf(As[buf][r + 8][kb + t]);
                a[mi][2] = f2tf(As[buf][r][kb + 4 + t]);
                a[mi][3] = f2tf(As[buf][r + 8][kb + 4 + t]);
            }
#pragma unroll
            for (int ni = 0; ni < 8; ni++) {
                int cn = n0 + ni * 8 + g;
                bb[ni][0] = f2tf(Bs[buf][kb + t][cn]);
                bb[ni][1] = f2tf(Bs[buf][kb + 4 + t][cn]);
            }
#pragma unroll
            for (int mi = 0; mi < 2; mi++)
#pragma unroll
                for (int ni = 0; ni < 8; ni++)
                    mma_tf32(acc[mi][ni], a[mi][0], a[mi][1], a[mi][2], a[mi][3],
                             bb[ni][0], bb[ni][1]);
        }

        if (kt + 1 < NKT) {
            storeA(buf ^ 1, kt + 1);
            cp_wait<0>();
        }
        __syncthreads();
    }

    float* Ob = Opre + (size_t)b * Sq * Dm;
    const int rbase = qb + m0;
    const int cbase = n0;
#pragma unroll
    for (int mi = 0; mi < 2; mi++) {
#pragma unroll
        for (int ni = 0; ni < 8; ni++) {
            int r = rbase + mi * 16 + g;
            int c = cbase + ni * 8 + 2 * t;
            float2 v0 = { acc[mi][ni][0], acc[mi][ni][1] };
            float2 v1 = { acc[mi][ni][2], acc[mi][ni][3] };
            *(float2*)&Ob[(size_t)r * Dm + c]       = v0;
            *(float2*)&Ob[(size_t)(r + 8) * Dm + c] = v1;
        }
    }
}

// =============================================================================
// Launch
// =============================================================================
extern "C" void kernel_launch(void* const* d_in, const int* in_sizes, int n_in,
                              void* d_out, int out_size)
{
    (void)in_sizes; (void)n_in; (void)out_size;
    const float* query = (const float*)d_in[0];
    const float* key   = (const float*)d_in[1];
    const float* value = (const float*)d_in[2];
    const float* W_q   = (const float*)d_in[3];
    const float* b_q   = (const float*)d_in[4];
    const float* W_k   = (const float*)d_in[5];
    const float* b_k   = (const float*)d_in[6];
    const float* W_v   = (const float*)d_in[7];
    const float* b_v   = (const float*)d_in[8];
    const float* W_o   = (const float*)d_in[9];
    const float* b_o   = (const float*)d_in[10];

    float* out = (float*)d_out;                 // (B,S,D)
    float* avg = out + OUT0_ELEMS;              // (B,S,S)

    float *pQ, *pK, *pV, *pE, *pO, *pZp, *pRZ;
    cudaGetSymbolAddress((void**)&pQ,  g_Q);
    cudaGetSymbolAddress((void**)&pK,  g_K);
    cudaGetSymbolAddress((void**)&pV,  g_V);
    cudaGetSymbolAddress((void**)&pE,  g_E);
    cudaGetSymbolAddress((void**)&pO,  g_O);
    cudaGetSymbolAddress((void**)&pZp, g_Zp);
    cudaGetSymbolAddress((void**)&pRZ, g_RZ);

    const int gemm_smem = (STAGES * 128 * 20 + STAGES * 16 * 136) * 4;
    cudaFuncSetAttribute(qkv_proj_kernel,
        cudaFuncAttributeMaxDynamicSharedMemorySize, gemm_smem);
    cudaFuncSetAttribute(oproj_kernel,
        cudaFuncAttributeMaxDynamicSharedMemorySize, gemm_smem);

    // 1: fused Q/K/V projections (one launch, 768 CTAs)
    {
        dim3 grid(Dm / 128, NTOK / 128, 3);
        qkv_proj_kernel<<<grid, 128, gemm_smem>>>(
            query, key, value, W_q, W_k, W_v, b_q, b_k, b_v, pQ, pK, pV);
    }

    // 2: E = exp(Q@K^T / 8) + row-sum partials
    {
        const int smem = 2 * 128 * 68 * 4;   // 69632 B
        cudaFuncSetAttribute(scores_tc_kernel,
            cudaFuncAttributeMaxDynamicSharedMemorySize, smem);
        dim3 grid(Sq / 128, Sq / 128, Bsz * Hh);
        scores_tc_kernel<<<grid, 256, smem>>>(pQ, pK, pE, pZp);
    }

    // 3: deterministic Z reduce -> 0.25/Z
    zred_kernel<<<NROWS / 256, 256>>>(pZp, pRZ);

    // 4: fused avg_attn production + avg@V (grid 256, occ 2)
    {
        const int smem = AV_SMEM_FLOATS * 4;  // 45056 B
        cudaFuncSetAttribute(avgv_fused_kernel,
            cudaFuncAttributeMaxDynamicSharedMemorySize, smem);
        dim3 grid(1, Sq / 64, Bsz);
        avgv_fused_kernel<<<grid, 256, smem>>>(pE, pRZ, pV, avg, pO);
    }

    // 5: final projection out = Opre @ W_o + b_o
    {
        dim3 grid(Dm / 128, NTOK / 128, 1);
        oproj_kernel<<<grid, 128, gemm_smem>>>(pO, W_o, out, b_o);
    }
}